// round 9
// baseline (speedup 1.0000x reference)
#include <cuda_runtime.h>
#include <cstddef>

// Problem constants (fixed by the dataset)
#define BATCH 4
#define CH    32
#define HH    120
#define WW    160
#define NXc   160
#define NYc   160
#define NZc   64
#define NVOX  (NXc * NYc * NZc)     // 1,638,400
#define HW    (HH * WW)             // 19,200

#define CH_SPLIT  2                 // threads sharing one voxel-group
#define CH_PER_T  (CH / CH_SPLIT)   // 16 channels per thread

// Channel-transposed features: [B][HW][C] — one pixel's 32 channels are one
// 128B cache line. Filled by transpose_kernel each launch (deterministic).
__device__ __align__(128) float g_tfeat[BATCH * HW * CH];

// ---------------------------------------------------------------------------
// Pre-pass: [B,C,H,W] -> [B,HW,C]. One thread per (b,pixel): 32 coalesced
// reads (stride HW across c, consecutive p across lanes), one 128B contiguous
// write per thread. ~2x9.8MB of traffic, a few microseconds.
// ---------------------------------------------------------------------------
__global__ __launch_bounds__(256) void transpose_kernel(
    const float* __restrict__ features)
{
    int t = blockIdx.x * blockDim.x + threadIdx.x;
    if (t >= BATCH * HW) return;
    int b = t / HW;
    int p = t - b * HW;

    const float* src = features + (size_t)b * CH * HW + p;
    float* dst = g_tfeat + (size_t)t * CH;

#pragma unroll
    for (int c4 = 0; c4 < CH; c4 += 4) {
        float4 o;
        o.x = __ldg(src + (size_t)(c4 + 0) * HW);
        o.y = __ldg(src + (size_t)(c4 + 1) * HW);
        o.z = __ldg(src + (size_t)(c4 + 2) * HW);
        o.w = __ldg(src + (size_t)(c4 + 3) * HW);
        *reinterpret_cast<float4*>(dst + c4) = o;
    }
}

// ---------------------------------------------------------------------------
// Main kernel. One thread: 4 consecutive z-voxels x 16 channels.
//  * gathers are LDG.128 from the channel-contiguous transposed features
//    (4 vector loads per 4-channel chunk, <=4 lines per thread total)
//  * 4x4 register transpose -> coalesced float4 stores per channel
//  * loads predicated on frustum validity (~74% of voxels invalid)
//  * __stcs streaming stores keep the 865MB output out of L2
//
// Projection math uses explicit IEEE-rounded intrinsics to bit-match the XLA
// reference (verified rel_err == 0.0 in R6/R7/R8):
//   world  = coords*vs + origin          (separate mul, add — NO fma)
//   camera = sum_j P[i,j]*world[j]       (rounded products, ascending adds)
//   u      = camera_x / camera_z         (IEEE correctly-rounded divide)
//   px     = round-half-even(u)          (__float2int_rn == jnp.round)
// ---------------------------------------------------------------------------
__global__ __launch_bounds__(256, 8) void backproject_kernel(
    const float* __restrict__ origin,      // [B,3]
    const float* __restrict__ projection,  // [B,3,4]
    const float* __restrict__ voxel_size,  // [1]
    float* __restrict__ out)               // volume [B,C,NVOX] ++ valid [B,NVOX]
{
    const int groups_per_batch = NVOX / 4;             // 409,600
    int gid = blockIdx.x * blockDim.x + threadIdx.x;
    if (gid >= BATCH * CH_SPLIT * groups_per_batch) return;

    int r  = gid % groups_per_batch;          // voxel group within batch
    int bh = gid / groups_per_batch;          // b * CH_SPLIT + h
    int h  = bh % CH_SPLIT;                   // channel half
    int b  = bh / CH_SPLIT;

    int v0 = r * 4;                 // base voxel index within batch
    int k  = v0 & (NZc - 1);        // z (NZ=64, 4-aligned chunks)
    int ij = v0 >> 6;               // i*NY + j
    int j  = ij % NYc;
    int i  = ij / NYc;

    const float vs = __ldg(voxel_size);
    const float* P = projection + b * 12;
    float P00 = __ldg(P + 0),  P01 = __ldg(P + 1),  P02 = __ldg(P + 2),  P03 = __ldg(P + 3);
    float P10 = __ldg(P + 4),  P11 = __ldg(P + 5),  P12 = __ldg(P + 6),  P13 = __ldg(P + 7);
    float P20 = __ldg(P + 8),  P21 = __ldg(P + 9),  P22 = __ldg(P + 10), P23 = __ldg(P + 11);

    float ox = __ldg(origin + b * 3 + 0);
    float oy = __ldg(origin + b * 3 + 1);
    float oz = __ldg(origin + b * 3 + 2);

    // world x/y: separately-rounded mul then add (matches coords*vs + origin)
    float wx = __fadd_rn(__fmul_rn((float)i, vs), ox);
    float wy = __fadd_rn(__fmul_rn((float)j, vs), oy);

    int  fidx[4];
    bool ok[4];
#pragma unroll
    for (int m = 0; m < 4; ++m) {
        float wz = __fadd_rn(__fmul_rn((float)(k + m), vs), oz);

        // camera_i = ((P_i0*wx + P_i1*wy) + P_i2*wz) + P_i3, each op rounded,
        // ascending j, no contraction.
        float cx = __fadd_rn(__fadd_rn(__fadd_rn(__fmul_rn(P00, wx),
                                                  __fmul_rn(P01, wy)),
                                        __fmul_rn(P02, wz)), P03);
        float cy = __fadd_rn(__fadd_rn(__fadd_rn(__fmul_rn(P10, wx),
                                                  __fmul_rn(P11, wy)),
                                        __fmul_rn(P12, wz)), P13);
        float cz = __fadd_rn(__fadd_rn(__fadd_rn(__fmul_rn(P20, wx),
                                                  __fmul_rn(P21, wy)),
                                        __fmul_rn(P22, wz)), P23);

        float u = __fdiv_rn(cx, cz);   // IEEE rn divide (immune to fast-math)
        float v = __fdiv_rn(cy, cz);
        int ipx = __float2int_rn(u);   // round-half-even == jnp.round
        int ipy = __float2int_rn(v);
        ok[m] = (ipx >= 0) && (ipy >= 0) && (ipx < WW) && (ipy < HH) && (cz > 0.0f);
        int cpx = min(max(ipx, 0), WW - 1);
        int cpy = min(max(ipy, 0), HH - 1);
        fidx[m] = cpy * WW + cpx;
    }

    const int c0 = h * CH_PER_T;
    float* vol = out + ((size_t)b * CH + c0) * NVOX + v0;
    const bool anyok = ok[0] | ok[1] | ok[2] | ok[3];

    if (anyok) {
        // Channel-contiguous gather rows for the 4 voxels of this group.
        const float* t0 = g_tfeat + ((size_t)b * HW + fidx[0]) * CH + c0;
        const float* t1 = g_tfeat + ((size_t)b * HW + fidx[1]) * CH + c0;
        const float* t2 = g_tfeat + ((size_t)b * HW + fidx[2]) * CH + c0;
        const float* t3 = g_tfeat + ((size_t)b * HW + fidx[3]) * CH + c0;
        const float4 zero4 = make_float4(0.f, 0.f, 0.f, 0.f);

#pragma unroll
        for (int cc = 0; cc < CH_PER_T; cc += 4) {
            // Predicated vector loads: channels [c0+cc .. c0+cc+3] of each voxel.
            float4 a0 = ok[0] ? *reinterpret_cast<const float4*>(t0 + cc) : zero4;
            float4 a1 = ok[1] ? *reinterpret_cast<const float4*>(t1 + cc) : zero4;
            float4 a2 = ok[2] ? *reinterpret_cast<const float4*>(t2 + cc) : zero4;
            float4 a3 = ok[3] ? *reinterpret_cast<const float4*>(t3 + cc) : zero4;
            // 4x4 register transpose -> per-channel voxel vectors.
            __stcs(reinterpret_cast<float4*>(vol + (size_t)(cc + 0) * NVOX),
                   make_float4(a0.x, a1.x, a2.x, a3.x));
            __stcs(reinterpret_cast<float4*>(vol + (size_t)(cc + 1) * NVOX),
                   make_float4(a0.y, a1.y, a2.y, a3.y));
            __stcs(reinterpret_cast<float4*>(vol + (size_t)(cc + 2) * NVOX),
                   make_float4(a0.z, a1.z, a2.z, a3.z));
            __stcs(reinterpret_cast<float4*>(vol + (size_t)(cc + 3) * NVOX),
                   make_float4(a0.w, a1.w, a2.w, a3.w));
        }
    } else {
        const float4 zero = make_float4(0.f, 0.f, 0.f, 0.f);
#pragma unroll 4
        for (int c = 0; c < CH_PER_T; ++c)
            __stcs(reinterpret_cast<float4*>(vol + (size_t)c * NVOX), zero);
    }

    if (h == 0) {
        float* vout = out + (size_t)BATCH * CH * NVOX + (size_t)b * NVOX + v0;
        __stcs(reinterpret_cast<float4*>(vout),
               make_float4(ok[0] ? 1.f : 0.f, ok[1] ? 1.f : 0.f,
                           ok[2] ? 1.f : 0.f, ok[3] ? 1.f : 0.f));
    }
}

extern "C" void kernel_launch(void* const* d_in, const int* in_sizes, int n_in,
                              void* d_out, int out_size)
{
    // Expected metadata order: origin[12], projection[48], features[2457600],
    // voxel_size[1]. Identify tensors by unique sizes as a guard.
    const float* origin     = (const float*)d_in[0];
    const float* projection = (const float*)d_in[1];
    const float* features   = (const float*)d_in[2];
    const float* voxel_size = (const float*)d_in[3];
    for (int t = 0; t < n_in; ++t) {
        if (in_sizes[t] == BATCH * CH * HH * WW) features   = (const float*)d_in[t];
        else if (in_sizes[t] == BATCH * 12)      projection = (const float*)d_in[t];
        else if (in_sizes[t] == BATCH * 3)       origin     = (const float*)d_in[t];
    }
    float* out = (float*)d_out;

    // Pass 1: channel-transpose features into g_tfeat.
    const int tp_threads = BATCH * HW;                       // 76,800
    transpose_kernel<<<(tp_threads + 255) / 256, 256>>>(features);

    // Pass 2: backproject.
    const int total_threads = BATCH * CH_SPLIT * (NVOX / 4); // 3,276,800
    const int block = 256;
    const int grid  = (total_threads + block - 1) / block;   // 12800
    backproject_kernel<<<grid, block>>>(origin, projection, voxel_size, out);
}

// round 10
// speedup vs baseline: 1.2691x; 1.2691x over previous
#include <cuda_runtime.h>
#include <cstddef>

// Problem constants (fixed by the dataset)
#define BATCH 4
#define CH    32
#define HH    120
#define WW    160
#define NXc   160
#define NYc   160
#define NZc   64
#define NVOX  (NXc * NYc * NZc)     // 1,638,400
#define HW    (HH * WW)             // 19,200

#define CH_SPLIT  4                 // threads sharing one voxel-group
#define CH_PER_T  (CH / CH_SPLIT)   // 8 channels per thread

// One thread handles 4 consecutive z-voxels (z innermost / contiguous in the
// output) x 8 channels -> every per-channel store is a coalesced float4.
// Channel work is split across 4 threads per voxel-group to shorten the
// LDG->STG dependency chain (R7->R8 showed chain-halving gave -23us; this
// halves it again). Projection is recomputed per thread (~40 FLOPs, free at
// fma=7%). Gathers stay in the native [B,C,H,W] layout: adjacent lanes sweep
// nearby pixels within one channel plane, so scalar LDGs are warp-coherent
// (the R9 [HW][C]-transpose experiment proved the transposed layout is WORSE).
//
// __launch_bounds__(256, 8) keeps regs <= 32 -> 64-warp occupancy ceiling.
//
// Projection math uses explicit IEEE-rounded intrinsics to bit-match the XLA
// reference (verified rel_err == 0.0 in R6-R9):
//   world  = coords*vs + origin          (separate mul, add — NO fma)
//   camera = sum_j P[i,j]*world[j]       (rounded products, ascending adds)
//   u      = camera_x / camera_z         (IEEE correctly-rounded divide)
//   px     = round-half-even(u)          (__float2int_rn == jnp.round)
__global__ __launch_bounds__(256, 8) void backproject_kernel(
    const float* __restrict__ origin,      // [B,3]
    const float* __restrict__ projection,  // [B,3,4]
    const float* __restrict__ features,    // [B,C,H,W]
    const float* __restrict__ voxel_size,  // [1]
    float* __restrict__ out)               // volume [B,C,NVOX] ++ valid [B,NVOX]
{
    const int groups_per_batch = NVOX / 4;             // 409,600
    int gid = blockIdx.x * blockDim.x + threadIdx.x;
    if (gid >= BATCH * CH_SPLIT * groups_per_batch) return;

    int r  = gid % groups_per_batch;          // voxel group within batch
    int bh = gid / groups_per_batch;          // b * CH_SPLIT + h
    int h  = bh % CH_SPLIT;                   // channel quarter
    int b  = bh / CH_SPLIT;

    int v0 = r * 4;                 // base voxel index within batch
    int k  = v0 & (NZc - 1);        // z (NZ=64, 4-aligned chunks)
    int ij = v0 >> 6;               // i*NY + j
    int j  = ij % NYc;
    int i  = ij / NYc;

    const float vs = __ldg(voxel_size);
    const float* P = projection + b * 12;
    float P00 = __ldg(P + 0),  P01 = __ldg(P + 1),  P02 = __ldg(P + 2),  P03 = __ldg(P + 3);
    float P10 = __ldg(P + 4),  P11 = __ldg(P + 5),  P12 = __ldg(P + 6),  P13 = __ldg(P + 7);
    float P20 = __ldg(P + 8),  P21 = __ldg(P + 9),  P22 = __ldg(P + 10), P23 = __ldg(P + 11);

    float ox = __ldg(origin + b * 3 + 0);
    float oy = __ldg(origin + b * 3 + 1);
    float oz = __ldg(origin + b * 3 + 2);

    // world x/y: separately-rounded mul then add (matches coords*vs + origin)
    float wx = __fadd_rn(__fmul_rn((float)i, vs), ox);
    float wy = __fadd_rn(__fmul_rn((float)j, vs), oy);

    int  fidx[4];
    bool ok[4];
#pragma unroll
    for (int m = 0; m < 4; ++m) {
        float wz = __fadd_rn(__fmul_rn((float)(k + m), vs), oz);

        // camera_i = ((P_i0*wx + P_i1*wy) + P_i2*wz) + P_i3, each op rounded,
        // ascending j, no contraction.
        float cx = __fadd_rn(__fadd_rn(__fadd_rn(__fmul_rn(P00, wx),
                                                  __fmul_rn(P01, wy)),
                                        __fmul_rn(P02, wz)), P03);
        float cy = __fadd_rn(__fadd_rn(__fadd_rn(__fmul_rn(P10, wx),
                                                  __fmul_rn(P11, wy)),
                                        __fmul_rn(P12, wz)), P13);
        float cz = __fadd_rn(__fadd_rn(__fadd_rn(__fmul_rn(P20, wx),
                                                  __fmul_rn(P21, wy)),
                                        __fmul_rn(P22, wz)), P23);

        float u = __fdiv_rn(cx, cz);   // IEEE rn divide (immune to fast-math)
        float v = __fdiv_rn(cy, cz);
        int ipx = __float2int_rn(u);   // round-half-even == jnp.round
        int ipy = __float2int_rn(v);
        ok[m] = (ipx >= 0) && (ipy >= 0) && (ipx < WW) && (ipy < HH) && (cz > 0.0f);
        int cpx = min(max(ipx, 0), WW - 1);
        int cpy = min(max(ipy, 0), HH - 1);
        fidx[m] = cpy * WW + cpx;
    }

    const int c0 = h * CH_PER_T;
    float* vol = out + ((size_t)b * CH + c0) * NVOX + v0;
    const bool anyok = ok[0] | ok[1] | ok[2] | ok[3];

    if (anyok) {
        const float* fb = features + ((size_t)b * CH + c0) * HW;
#pragma unroll
        for (int c = 0; c < CH_PER_T; ++c) {
            const float* fc = fb + (size_t)c * HW;
            float4 o = make_float4(0.f, 0.f, 0.f, 0.f);
            // Predicated loads: invalid lanes issue NO memory request.
            if (ok[0]) o.x = __ldg(fc + fidx[0]);
            if (ok[1]) o.y = __ldg(fc + fidx[1]);
            if (ok[2]) o.z = __ldg(fc + fidx[2]);
            if (ok[3]) o.w = __ldg(fc + fidx[3]);
            __stcs(reinterpret_cast<float4*>(vol + (size_t)c * NVOX), o);
        }
    } else {
        const float4 zero = make_float4(0.f, 0.f, 0.f, 0.f);
#pragma unroll
        for (int c = 0; c < CH_PER_T; ++c)
            __stcs(reinterpret_cast<float4*>(vol + (size_t)c * NVOX), zero);
    }

    if (h == 0) {
        float* vout = out + (size_t)BATCH * CH * NVOX + (size_t)b * NVOX + v0;
        __stcs(reinterpret_cast<float4*>(vout),
               make_float4(ok[0] ? 1.f : 0.f, ok[1] ? 1.f : 0.f,
                           ok[2] ? 1.f : 0.f, ok[3] ? 1.f : 0.f));
    }
}

extern "C" void kernel_launch(void* const* d_in, const int* in_sizes, int n_in,
                              void* d_out, int out_size)
{
    // Expected metadata order: origin[12], projection[48], features[2457600],
    // voxel_size[1]. Identify tensors by unique sizes as a guard.
    const float* origin     = (const float*)d_in[0];
    const float* projection = (const float*)d_in[1];
    const float* features   = (const float*)d_in[2];
    const float* voxel_size = (const float*)d_in[3];
    for (int t = 0; t < n_in; ++t) {
        if (in_sizes[t] == BATCH * CH * HH * WW) features   = (const float*)d_in[t];
        else if (in_sizes[t] == BATCH * 12)      projection = (const float*)d_in[t];
        else if (in_sizes[t] == BATCH * 3)       origin     = (const float*)d_in[t];
    }
    float* out = (float*)d_out;

    const int total_threads = BATCH * CH_SPLIT * (NVOX / 4); // 6,553,600
    const int block = 256;
    const int grid  = (total_threads + block - 1) / block;   // 25600
    backproject_kernel<<<grid, block>>>(origin, projection, features, voxel_size, out);
}